// round 14
// baseline (speedup 1.0000x reference)
#include <cuda_runtime.h>
#include <cuda_fp16.h>
#include <cstdint>

#define B_TOTAL 16384
#define NNODES  200
#define NEDGES  800
#define XF      2600
#define FEATR   2800
#define FEATP   2816           // K padded to 22*128
#define NT1     (FEATP / 128)  // 22

// ---------------- device scratch ----------------
__device__ __align__(16) __half g_a1h[(size_t)B_TOTAL * 128];
__device__ float g_ew[3];
__device__ float g_b1adj[128];
__device__ __align__(16) __half g_w1t[128 * FEATP];    // fp16, transposed [n][k]
__device__ __align__(16) __half g_w2t[128 * 128];
__device__ __align__(16) __half g_w3t[64 * 128];

// ---------------- helpers ----------------
__device__ __forceinline__ uint32_t smem_to_u32(const void* p) {
    uint32_t a;
    asm("{ .reg .u64 t; cvta.to.shared.u64 t, %1; cvt.u32.u64 %0, t; }" : "=r"(a) : "l"(p));
    return a;
}
#define SWZ(off) ((off) ^ (((off) >> 3) & 0x70))

__device__ __forceinline__ void ldsm4(uint32_t r[4], uint32_t addr) {
    asm volatile("ldmatrix.sync.aligned.m8n8.x4.shared.b16 {%0,%1,%2,%3}, [%4];"
                 : "=r"(r[0]), "=r"(r[1]), "=r"(r[2]), "=r"(r[3]) : "r"(addr));
}
__device__ __forceinline__ void mma16816h(float c[4], const uint32_t a[4],
                                          uint32_t b0, uint32_t b1) {
    asm volatile("mma.sync.aligned.m16n8k16.row.col.f32.f16.f16.f32 "
                 "{%0,%1,%2,%3}, {%4,%5,%6,%7}, {%8,%9}, {%0,%1,%2,%3};"
                 : "+f"(c[0]), "+f"(c[1]), "+f"(c[2]), "+f"(c[3])
                 : "r"(a[0]), "r"(a[1]), "r"(a[2]), "r"(a[3]), "r"(b0), "r"(b1));
}
__device__ __forceinline__ void cpa16(uint32_t dst, const void* src) {
    asm volatile("cp.async.cg.shared.global [%0], [%1], 16;" :: "r"(dst), "l"(src));
}
#define CPA_COMMIT() asm volatile("cp.async.commit_group;" ::: "memory")
#define CPA_WAIT0()  asm volatile("cp.async.wait_group 0;" ::: "memory")

__device__ __forceinline__ uint32_t packh2(float a, float b) {
    __half2 h = __floats2half2_rn(a, b);
    return *reinterpret_cast<uint32_t*>(&h);
}
// fast softplus: MUFU-backed (error ~1e-6 rel, far under budget)
__device__ __forceinline__ float softplusf(float x) {
    return fmaxf(x, 0.f) + __logf(1.f + __expf(-fabsf(x)));
}
// fast tanh: saturates correctly at +/-inf
__device__ __forceinline__ float fast_tanhf(float v) {
    float e = __expf(2.f * v);
    return 1.f - __fdividef(2.f, e + 1.f);
}

// ---------------- MMA over a 64-col K subtile: 2M x (NTILES*8) ----------------
template<int NTILES>
__device__ __forceinline__ void mma_chunk1(float (&C)[2][NTILES][4],
                                           uint32_t a_u, uint32_t b_u,
                                           int wm_base, int wn_base, int lane) {
    const int lr = (lane & 7) + ((lane >> 3) & 1) * 8;
    const int lh = (lane >> 4) * 16;
    #pragma unroll
    for (int kk = 0; kk < 4; kk++) {
        uint32_t a[2][4];
        #pragma unroll
        for (int mt = 0; mt < 2; mt++) {
            uint32_t off = SWZ((uint32_t)((wm_base + mt * 16 + lr) * 128 + kk * 32 + lh));
            ldsm4(a[mt], a_u + off);
        }
        #pragma unroll
        for (int ng = 0; ng < NTILES / 2; ng++) {
            uint32_t off = SWZ((uint32_t)((wn_base + ng * 16 + lr) * 128 + kk * 32 + lh));
            uint32_t b[4];
            ldsm4(b, b_u + off);
            #pragma unroll
            for (int half = 0; half < 2; half++) {
                const int nt = ng * 2 + half;
                #pragma unroll
                for (int mt = 0; mt < 2; mt++)
                    mma16816h(C[mt][nt], a[mt], b[half], b[half + 2]);
            }
        }
    }
}

// ================= single prep kernel, block roles =================
// blocks 0..447   : grid-stride weight transposes (W1 x-rows, W2, W3)
// blocks 448..547 : graph fold — 2 src nodes each, local degree recompute,
//                   write w1t rows [2600,2800) directly as fp16
// block  548      : ew + b1adj
#define TRB 448
__global__ void prep_kernel(const int* __restrict__ es, const int* __restrict__ ed,
                            const float* __restrict__ emb, const float* __restrict__ gcw,
                            const float* __restrict__ gcb,
                            const float* __restrict__ W1, const float* __restrict__ b1,
                            const float* __restrict__ W2, const float* __restrict__ W3) {
    const int b = blockIdx.x;
    const int tid = threadIdx.x;
    if (b < TRB) {
        const int gtid = b * 256 + tid;
        const int gsz = TRB * 256;
        const int T1 = 128 * FEATP, T2 = 128 * 128, T3 = 64 * 128;
        for (int i = gtid; i < T1 + T2 + T3; i += gsz) {
            float v;
            __half* ph;
            if (i < T1) {
                int k = i % FEATP;
                int n = i / FEATP;
                if (k >= XF && k < FEATR) continue;   // graph rows: filled by fold blocks
                v = (k < XF) ? W1[(size_t)k * 128 + n] : 0.f;
                ph = g_w1t + i;
            } else if (i < T1 + T2) {
                int j = i - T1;
                int n = j >> 7, k = j & 127;
                v = W2[k * 128 + n];
                ph = g_w2t + j;
            } else {
                int j = i - T1 - T2;
                int n = j >> 7, k = j & 127;
                v = W3[k * 64 + n];
                ph = g_w3t + j;
            }
            *ph = __float2half_rn(v);
        }
    } else if (b < TRB + 100) {
        __shared__ int ses[NEDGES], sed[NEDGES];
        __shared__ int cnto[NNODES], cnti[NNODES];
        __shared__ float ndst[NNODES];
        for (int i = tid; i < NEDGES; i += 256) { ses[i] = es[i]; sed[i] = ed[i]; }
        for (int n = tid; n < NNODES; n += 256) { cnto[n] = 0; cnti[n] = 0; }
        __syncthreads();
        for (int e = tid; e < NEDGES; e += 256) {
            atomicAdd(&cnto[ses[e]], 1);
            atomicAdd(&cnti[sed[e]], 1);
        }
        __syncthreads();
        for (int n = tid; n < NNODES; n += 256)
            ndst[n] = rsqrtf((float)max(cnti[n], 1));
        __syncthreads();
        const int s = (b - TRB) * 2 + (tid >> 7);
        const int n = tid & 127;
        const float nsrc = rsqrtf((float)max(cnto[s], 1));
        float acc = 0.f;
        for (int e = 0; e < NEDGES; e++) {
            if (ses[e] == s) {
                const int d = sed[e];
                acc += ndst[d] * W1[(size_t)(XF + d) * 128 + n];
            }
        }
        g_w1t[(size_t)n * FEATP + XF + s] = __float2half_rn(nsrc * acc);
    } else {
        // ew + b1adj
        if (tid < 3) {
            float s = 0.f;
            #pragma unroll
            for (int j = 0; j < 5; j++) s += emb[tid * 5 + j] * gcw[j];
            g_ew[tid] = s;
        }
        if (tid < 128) {
            float s0 = 0.f, s1 = 0.f;
            for (int d = 0; d < NNODES; d += 2) {
                s0 += W1[(size_t)(XF + d) * 128 + tid];
                s1 += W1[(size_t)(XF + d + 1) * 128 + tid];
            }
            g_b1adj[tid] = b1[tid] + gcb[0] * (s0 + s1);
        }
    }
}

// ================= GEMM1: a1 = softplus([x|hw] @ W1' + b1adj) -> fp16 =================
// K-chunk = 128 (two 64-col subtiles), 2-stage A (16KB) + 2-stage B (32KB).
#define G1_OFF_B1 0
#define G1_OFF_A  1024
#define G1_OFF_BW (1024 + 32768)
#define G1_SMEM   (1024 + 32768 + 65536)

__device__ __forceinline__ float4 app4(const int* p, float e0, float e1, float e2) {
    int4 a = *(const int4*)p;
    return make_float4(a.x == 0 ? e0 : (a.x == 1 ? e1 : e2),
                       a.y == 0 ? e0 : (a.y == 1 ? e1 : e2),
                       a.z == 0 ? e0 : (a.z == 1 ? e1 : e2),
                       a.w == 0 ? e0 : (a.w == 1 ? e1 : e2));
}

__device__ __forceinline__ void g1_lda(float4 (&pf)[4], const float* __restrict__ xr,
                                       const int* __restrict__ ar,
                                       float e0, float e1, float e2, int k0, int kq0) {
    if (k0 + 63 < XF) {
        #pragma unroll
        for (int j = 0; j < 4; j++) pf[j] = *(const float4*)(xr + k0 + kq0 + j * 4);
    } else {
        #pragma unroll
        for (int j = 0; j < 4; j++) {
            const int k = k0 + kq0 + j * 4;
            if (k + 3 < XF)       pf[j] = *(const float4*)(xr + k);
            else if (k < FEATR)   pf[j] = app4(ar + (k - XF), e0, e1, e2);
            else                  pf[j] = make_float4(0.f, 0.f, 0.f, 0.f);
        }
    }
}
__device__ __forceinline__ void g1_sta(const float4 (&pf)[4], char* Ab, int row, int kq0) {
    #pragma unroll
    for (int q = 0; q < 2; q++) {
        const float4 f0 = pf[q * 2], f1 = pf[q * 2 + 1];
        uint4 h;
        h.x = packh2(f0.x, f0.y);
        h.y = packh2(f0.z, f0.w);
        h.z = packh2(f1.x, f1.y);
        h.w = packh2(f1.z, f1.w);
        const uint32_t off = SWZ((uint32_t)(row * 128 + (kq0 + q * 8) * 2));
        *(uint4*)(Ab + off) = h;
    }
}

__device__ __forceinline__ void g1_ldb(const uint32_t (&bofs)[4],
                                       const __half* const (&gw)[4],
                                       uint32_t dst, int koff) {
    #pragma unroll
    for (int i = 0; i < 4; i++) cpa16(dst + bofs[i], gw[i] + koff);
}

__global__ __launch_bounds__(256, 2)
void gemm1_kernel(const float* __restrict__ x, const int* __restrict__ apps) {
    extern __shared__ char sm[];
    const uint32_t su = smem_to_u32(sm);
    const int tid = threadIdx.x;
    const int wid = tid >> 5;
    const int lane = tid & 31;
    const int b0 = blockIdx.x * 64;

    float* sb1 = (float*)(sm + G1_OFF_B1);
    if (tid < 128) sb1[tid] = g_b1adj[tid];

    char* pA[2] = { sm + G1_OFF_A, sm + G1_OFF_A + 16384 };
    const uint32_t uA[2] = { su + G1_OFF_A, su + G1_OFF_A + 16384 };
    const uint32_t uB[2] = { su + G1_OFF_BW, su + G1_OFF_BW + 32768 };

    const int arow = tid >> 2;
    const int kq0  = (tid & 3) * 16;
    const float* xr = x + (size_t)(b0 + arow) * XF;
    const int*   ar = apps + (size_t)(b0 + arow) * NNODES;
    const float e0 = g_ew[0], e1 = g_ew[1], e2 = g_ew[2];

    uint32_t bofs[4];
    const __half* gw[4];
    #pragma unroll
    for (int i = 0; i < 4; i++) {
        const int v = tid + i * 256;
        bofs[i] = SWZ((uint32_t)((v >> 3) * 128 + (v & 7) * 16));
        gw[i] = g_w1t + (size_t)(v >> 3) * FEATP + (v & 7) * 8;
    }

    const int wm = (wid >> 2) * 32;
    const int wn = (wid & 3) * 32;

    float C[2][4][4];
    #pragma unroll
    for (int i = 0; i < 2; i++)
        #pragma unroll
        for (int j = 0; j < 4; j++)
            #pragma unroll
            for (int q = 0; q < 4; q++) C[i][j][q] = 0.f;

    float4 pf[4];
    // ---- prologue ----
    g1_ldb(bofs, gw, uB[0], 0);
    g1_ldb(bofs, gw, uB[0] + 16384, 64);
    CPA_COMMIT();
    g1_lda(pf, xr, ar, e0, e1, e2, 0, kq0);
    g1_sta(pf, pA[0], arow, kq0);
    g1_lda(pf, xr, ar, e0, e1, e2, 64, kq0);
    g1_sta(pf, pA[0] + 8192, arow, kq0);
    CPA_WAIT0();
    __syncthreads();

    // ---- mainloop: 22 iterations of K=128 ----
    for (int t = 0; t < NT1; t++) {
        const int cur = t & 1;
        const int nb = cur ^ 1;
        const bool more = (t + 1 < NT1);
        float4 pfl[4];
        if (more) {
            const int koff = (t + 1) * 128;
            g1_ldb(bofs, gw, uB[nb], koff);
            g1_ldb(bofs, gw, uB[nb] + 16384, koff + 64);
            CPA_COMMIT();
            g1_lda(pfl, xr, ar, e0, e1, e2, koff, kq0);
        }
        mma_chunk1<4>(C, uA[cur], uB[cur], wm, wn, lane);
        if (more) {
            g1_sta(pfl, pA[nb], arow, kq0);
            g1_lda(pfl, xr, ar, e0, e1, e2, (t + 1) * 128 + 64, kq0);
        }
        mma_chunk1<4>(C, uA[cur] + 8192, uB[cur] + 16384, wm, wn, lane);
        if (more) {
            g1_sta(pfl, pA[nb] + 8192, arow, kq0);
            CPA_WAIT0();
        }
        __syncthreads();
    }

    // ---- epilogue: bias + softplus -> g_a1h (fp16) ----
    {
        const int r0 = wm + (lane >> 2);
        const int c0 = wn + (lane & 3) * 2;
        #pragma unroll
        for (int mt = 0; mt < 2; mt++) {
            #pragma unroll
            for (int nt = 0; nt < 4; nt++) {
                const int c = c0 + nt * 8;
                const float bb0 = sb1[c], bb1 = sb1[c + 1];
                uint32_t p01 = packh2(softplusf(C[mt][nt][0] + bb0),
                                      softplusf(C[mt][nt][1] + bb1));
                uint32_t p23 = packh2(softplusf(C[mt][nt][2] + bb0),
                                      softplusf(C[mt][nt][3] + bb1));
                *(uint32_t*)(g_a1h + (size_t)(b0 + r0 + mt * 16) * 128 + c) = p01;
                *(uint32_t*)(g_a1h + (size_t)(b0 + r0 + mt * 16 + 8) * 128 + c) = p23;
            }
        }
    }
}

// ================= kernel 2: layers 2-4 =================
#define M2_OFF_B2 0
#define M2_OFF_B3 512
#define M2_OFF_B4 768
#define M2_OFF_W4 1024
#define M2_OFF_A  2048                       // a tiles: 2 x 8KB (a1 -> a2 -> a3)
#define M2_OFF_W2 (2048 + 16384)             // 2 x 16KB
#define M2_OFF_W3 (2048 + 16384 + 32768)     // 2 x 8KB
#define M2_SMEM   (2048 + 16384 + 32768 + 16384)

__device__ __forceinline__ void m2_cpa_W(const __half* __restrict__ W, int ldk,
                                         int k0, uint32_t dst, int nrows, int tid) {
    const int nv = nrows * 8;
    for (int v = tid; v < nv; v += 256) {
        const int n = v >> 3, kq = (v & 7) * 8;
        cpa16(dst + SWZ((uint32_t)(n * 128 + kq * 2)), W + (size_t)n * ldk + k0 + kq);
    }
}

__device__ __forceinline__ void m2_epi(float (&C)[2][4][4], const float* bias,
                                       char* dst, int wm_base, int wn_base, int lane) {
    const int r0 = wm_base + (lane >> 2);
    const int c0 = wn_base + (lane & 3) * 2;
    #pragma unroll
    for (int mt = 0; mt < 2; mt++) {
        #pragma unroll
        for (int nt = 0; nt < 4; nt++) {
            const int n = c0 + nt * 8;
            const int chunk = n >> 6, col = n & 63;
            const float b0 = bias[n], b1 = bias[n + 1];
            char* td = dst + chunk * 8192;
            uint32_t p01 = packh2(softplusf(C[mt][nt][0] + b0),
                                  softplusf(C[mt][nt][1] + b1));
            uint32_t p23 = packh2(softplusf(C[mt][nt][2] + b0),
                                  softplusf(C[mt][nt][3] + b1));
            *(uint32_t*)(td + SWZ((uint32_t)((r0 + mt * 16) * 128 + col * 2))) = p01;
            *(uint32_t*)(td + SWZ((uint32_t)((r0 + mt * 16 + 8) * 128 + col * 2))) = p23;
        }
    }
}

__global__ __launch_bounds__(256, 2)
void mlp2_kernel(const float* __restrict__ b2g, const float* __restrict__ b3g,
                 const float* __restrict__ b4g, const float* __restrict__ W4g,
                 float* __restrict__ out) {
    extern __shared__ char sm[];
    const uint32_t su = smem_to_u32(sm);
    const int tid = threadIdx.x;
    const int wid = tid >> 5;
    const int lane = tid & 31;
    const int b0 = blockIdx.x * 64;

    float* sb2 = (float*)(sm + M2_OFF_B2);
    float* sb3 = (float*)(sm + M2_OFF_B3);
    float* sb4 = (float*)(sm + M2_OFF_B4);
    float* sW4 = (float*)(sm + M2_OFF_W4);
    if (tid < 128) { sb2[tid] = b2g[tid]; sW4[tid] = W4g[tid]; }
    if (tid < 64) sb3[tid] = b3g[tid];
    if (tid < 2) sb4[tid] = b4g[tid];

    const uint32_t uA[2]  = { su + M2_OFF_A,  su + M2_OFF_A + 8192 };
    const uint32_t uW2[2] = { su + M2_OFF_W2, su + M2_OFF_W2 + 16384 };
    const uint32_t uW3[2] = { su + M2_OFF_W3, su + M2_OFF_W3 + 8192 };

    // load everything up front: a1, W2, W3
    m2_cpa_W(g_a1h + (size_t)b0 * 128, 128, 0,  uA[0], 64, tid);
    m2_cpa_W(g_a1h + (size_t)b0 * 128, 128, 64, uA[1], 64, tid);
    m2_cpa_W(g_w2t, 128, 0,  uW2[0], 128, tid);
    m2_cpa_W(g_w2t, 128, 64, uW2[1], 128, tid);
    m2_cpa_W(g_w3t, 128, 0,  uW3[0], 64, tid);
    m2_cpa_W(g_w3t, 128, 64, uW3[1], 64, tid);
    CPA_COMMIT();
    CPA_WAIT0();
    __syncthreads();

    const int wm = (wid >> 2) * 32;
    const int wn = (wid & 3) * 32;

    // GEMM2
    float C[2][4][4];
    #pragma unroll
    for (int i = 0; i < 2; i++)
        #pragma unroll
        for (int j = 0; j < 4; j++)
            #pragma unroll
            for (int q = 0; q < 4; q++) C[i][j][q] = 0.f;
    #pragma unroll
    for (int c = 0; c < 2; c++)
        mma_chunk1<4>(C, uA[c], uW2[c], wm, wn, lane);
    __syncthreads();

    // epi2 -> a2 tiles (A region)
    m2_epi(C, sb2, sm + M2_OFF_A, wm, wn, lane);
    __syncthreads();

    // GEMM3 (N=64), warp tile 32x16
    const int wn3 = (wid & 3) * 16;
    float C3[2][2][4];
    #pragma unroll
    for (int i = 0; i < 2; i++)
        #pragma unroll
        for (int j = 0; j < 2; j++)
            #pragma unroll
            for (int q = 0; q < 4; q++) C3[i][j][q] = 0.f;
    #pragma unroll
    for (int c = 0; c < 2; c++)
        mma_chunk1<2>(C3, uA[c], uW3[c], wm, wn3, lane);
    __syncthreads();

    // epi3: tanhshrink -> a3 fp32 [64][68] (A region; spills into W2 region, W2 dead)
    {
        float* a3 = (float*)(sm + M2_OFF_A);
        const int r0 = wm + (lane >> 2);
        const int c0 = wn3 + (lane & 3) * 2;
        #pragma unroll
        for (int mt = 0; mt < 2; mt++) {
            #pragma unroll
            for (int nt = 0; nt < 2; nt++) {
                const int n = c0 + nt * 8;
                const float b0v = sb3[n], b1v = sb3[n + 1];
                float v;
                v = C3[mt][nt][0] + b0v; a3[(r0 + mt * 16) * 68 + n]     = v - fast_tanhf(v);
                v = C3[mt][nt][1] + b1v; a3[(r0 + mt * 16) * 68 + n + 1] = v - fast_tanhf(v);
                v = C3[mt][nt][2] + b0v; a3[(r0 + mt * 16 + 8) * 68 + n]     = v - fast_tanhf(v);
                v = C3[mt][nt][3] + b1v; a3[(r0 + mt * 16 + 8) * 68 + n + 1] = v - fast_tanhf(v);
            }
        }
    }
    __syncthreads();

    // layer 4 + sigmoid
    if (tid < 128) {
        const float* a3 = (const float*)(sm + M2_OFF_A);
        const int row = tid >> 1;
        const int c = tid & 1;
        float s = sb4[c];
        #pragma unroll
        for (int k = 0; k < 64; k++) s += a3[row * 68 + k] * sW4[k * 2 + c];
        out[(size_t)(b0 + row) * 2 + c] = __fdividef(1.f, 1.f + __expf(-s));
    }
}

// ---------------- launch ----------------
extern "C" void kernel_launch(void* const* d_in, const int* in_sizes, int n_in,
                              void* d_out, int out_size) {
    const float* x    = (const float*)d_in[0];
    const int*   apps = (const int*)d_in[1];
    const int*   es   = (const int*)d_in[2];
    const int*   ed   = (const int*)d_in[3];
    const float* emb  = (const float*)d_in[4];
    const float* gcw  = (const float*)d_in[5];
    const float* gcb  = (const float*)d_in[6];
    const float* W1   = (const float*)d_in[7];
    const float* b1   = (const float*)d_in[8];
    const float* W2   = (const float*)d_in[9];
    const float* b2   = (const float*)d_in[10];
    const float* W3   = (const float*)d_in[11];
    const float* b3   = (const float*)d_in[12];
    const float* W4   = (const float*)d_in[13];
    const float* b4   = (const float*)d_in[14];
    float* out = (float*)d_out;

    cudaFuncSetAttribute(gemm1_kernel, cudaFuncAttributeMaxDynamicSharedMemorySize, G1_SMEM);
    cudaFuncSetAttribute(mlp2_kernel, cudaFuncAttributeMaxDynamicSharedMemorySize, M2_SMEM);

    prep_kernel<<<TRB + 101, 256>>>(es, ed, emb, gcw, gcb, W1, b1, W2, W3);
    gemm1_kernel<<<B_TOTAL / 64, 256, G1_SMEM>>>(x, apps);
    mlp2_kernel<<<B_TOTAL / 64, 256, M2_SMEM>>>(b2, b3, b4, W4, out);
}

// round 15
// speedup vs baseline: 1.1646x; 1.1646x over previous
#include <cuda_runtime.h>
#include <cuda_fp16.h>
#include <cstdint>

#define B_TOTAL 16384
#define NNODES  200
#define NEDGES  800
#define XF      2600
#define FEATR   2800
#define FEATP   2816           // K padded to 22*128
#define NT1     (FEATP / 128)  // 22

// ---------------- device scratch ----------------
__device__ __align__(16) __half g_a1h[(size_t)B_TOTAL * 128];
__device__ float g_norm_dst[NNODES];
__device__ float g_norm_src[NNODES];
__device__ float g_ew[3];
__device__ float g_b1adj[128];
__device__ __align__(16) float g_w1gp[NNODES * 128];   // M^T @ W1g, fp32 accum
__device__ __align__(16) __half g_w1t[128 * FEATP];    // fp16, transposed [n][k]
__device__ __align__(16) __half g_w2t[128 * 128];
__device__ __align__(16) __half g_w3t[64 * 128];

// ---------------- helpers ----------------
__device__ __forceinline__ uint32_t smem_to_u32(const void* p) {
    uint32_t a;
    asm("{ .reg .u64 t; cvta.to.shared.u64 t, %1; cvt.u32.u64 %0, t; }" : "=r"(a) : "l"(p));
    return a;
}
#define SWZ(off) ((off) ^ (((off) >> 3) & 0x70))

__device__ __forceinline__ void ldsm4(uint32_t r[4], uint32_t addr) {
    asm volatile("ldmatrix.sync.aligned.m8n8.x4.shared.b16 {%0,%1,%2,%3}, [%4];"
                 : "=r"(r[0]), "=r"(r[1]), "=r"(r[2]), "=r"(r[3]) : "r"(addr));
}
__device__ __forceinline__ void mma16816h(float c[4], const uint32_t a[4],
                                          uint32_t b0, uint32_t b1) {
    asm volatile("mma.sync.aligned.m16n8k16.row.col.f32.f16.f16.f32 "
                 "{%0,%1,%2,%3}, {%4,%5,%6,%7}, {%8,%9}, {%0,%1,%2,%3};"
                 : "+f"(c[0]), "+f"(c[1]), "+f"(c[2]), "+f"(c[3])
                 : "r"(a[0]), "r"(a[1]), "r"(a[2]), "r"(a[3]), "r"(b0), "r"(b1));
}
__device__ __forceinline__ void cpa16(uint32_t dst, const void* src) {
    asm volatile("cp.async.cg.shared.global [%0], [%1], 16;" :: "r"(dst), "l"(src));
}
#define CPA_COMMIT() asm volatile("cp.async.commit_group;" ::: "memory")
#define CPA_WAIT0()  asm volatile("cp.async.wait_group 0;" ::: "memory")

__device__ __forceinline__ uint32_t packh2(float a, float b) {
    __half2 h = __floats2half2_rn(a, b);
    return *reinterpret_cast<uint32_t*>(&h);
}
// fast softplus: MUFU-backed (error ~1e-6 rel, far under fp16 budget)
__device__ __forceinline__ float softplusf(float x) {
    return fmaxf(x, 0.f) + __logf(1.f + __expf(-fabsf(x)));
}
// fast tanh: saturates correctly at +/-inf
__device__ __forceinline__ float fast_tanhf(float v) {
    float e = __expf(2.f * v);
    return 1.f - __fdividef(2.f, e + 1.f);
}

// ---------------- MMA over a 64-col K subtile: 2M x (NTILES*8) ----------------
template<int NTILES>
__device__ __forceinline__ void mma_chunk1(float (&C)[2][NTILES][4],
                                           uint32_t a_u, uint32_t b_u,
                                           int wm_base, int wn_base, int lane) {
    const int lr = (lane & 7) + ((lane >> 3) & 1) * 8;
    const int lh = (lane >> 4) * 16;
    #pragma unroll
    for (int kk = 0; kk < 4; kk++) {
        uint32_t a[2][4];
        #pragma unroll
        for (int mt = 0; mt < 2; mt++) {
            uint32_t off = SWZ((uint32_t)((wm_base + mt * 16 + lr) * 128 + kk * 32 + lh));
            ldsm4(a[mt], a_u + off);
        }
        #pragma unroll
        for (int ng = 0; ng < NTILES / 2; ng++) {
            uint32_t off = SWZ((uint32_t)((wn_base + ng * 16 + lr) * 128 + kk * 32 + lh));
            uint32_t b[4];
            ldsm4(b, b_u + off);
            #pragma unroll
            for (int half = 0; half < 2; half++) {
                const int nt = ng * 2 + half;
                #pragma unroll
                for (int mt = 0; mt < 2; mt++)
                    mma16816h(C[mt][nt], a[mt], b[half], b[half + 2]);
            }
        }
    }
}

// ================= prep1: degrees/norms/ew/bias-fold, zero W1gp =================
__global__ void prep1_kernel(const int* __restrict__ es, const int* __restrict__ ed,
                             const float* __restrict__ emb, const float* __restrict__ gcw,
                             const float* __restrict__ gcb,
                             const float* __restrict__ W1, const float* __restrict__ b1) {
    __shared__ int cnto[NNODES], cnti[NNODES];
    const int tid = threadIdx.x;
    for (int n = tid; n < NNODES; n += 256) { cnto[n] = 0; cnti[n] = 0; }
    __syncthreads();
    for (int e = tid; e < NEDGES; e += 256) {
        atomicAdd(&cnto[es[e]], 1);
        atomicAdd(&cnti[ed[e]], 1);
    }
    __syncthreads();
    for (int n = tid; n < NNODES; n += 256) {
        g_norm_dst[n] = rsqrtf((float)max(cnti[n], 1));
        g_norm_src[n] = rsqrtf((float)max(cnto[n], 1));
    }
    if (tid < 3) {
        float s = 0.f;
        #pragma unroll
        for (int j = 0; j < 5; j++) s += emb[tid * 5 + j] * gcw[j];
        g_ew[tid] = s;
    }
    for (int i = tid; i < NNODES * 128; i += 256) g_w1gp[i] = 0.f;
    if (tid < 128) {
        float s = 0.f;
        for (int d = 0; d < NNODES; d++) s += W1[(size_t)(XF + d) * 128 + tid];
        g_b1adj[tid] = b1[tid] + gcb[0] * s;
    }
}

// ================= prep2: weight transposes + edge atomics =================
__global__ void prep2_kernel(const int* __restrict__ es, const int* __restrict__ ed,
                             const float* __restrict__ W1, const float* __restrict__ W2,
                             const float* __restrict__ W3) {
    const int gtid = blockIdx.x * blockDim.x + threadIdx.x;
    const int gsz = gridDim.x * blockDim.x;
    for (int i = gtid; i < NEDGES * 128; i += gsz) {
        const int e = i >> 7, n = i & 127;
        const int s = es[e], d = ed[e];
        const float c = g_norm_src[s] * g_norm_dst[d];
        atomicAdd(&g_w1gp[s * 128 + n], c * W1[(size_t)(XF + d) * 128 + n]);
    }
    const int T1 = 128 * FEATP, T2 = 128 * 128, T3 = 64 * 128;
    for (int i = gtid; i < T1 + T2 + T3; i += gsz) {
        float v;
        __half* ph;
        if (i < T1) {
            int k = i % FEATP;
            int n = i / FEATP;
            if (k >= XF && k < FEATR) continue;
            v = (k < XF) ? W1[(size_t)k * 128 + n] : 0.f;
            ph = g_w1t + i;
        } else if (i < T1 + T2) {
            int j = i - T1;
            int n = j >> 7, k = j & 127;
            v = W2[k * 128 + n];
            ph = g_w2t + j;
        } else {
            int j = i - T1 - T2;
            int n = j >> 7, k = j & 127;
            v = W3[k * 64 + n];
            ph = g_w3t + j;
        }
        *ph = __float2half_rn(v);
    }
}

// ================= prep3: W1gp -> fp16 into w1t rows [2600,2800) =================
__global__ void prep3_kernel() {
    const int gtid = blockIdx.x * blockDim.x + threadIdx.x;
    if (gtid < NNODES * 128) {
        const int s = gtid >> 7, n = gtid & 127;
        g_w1t[(size_t)n * FEATP + XF + s] = __float2half_rn(g_w1gp[gtid]);
    }
}

// ================= GEMM1: a1 = softplus([x|hw] @ W1' + b1adj) -> fp16 =================
// K-chunk = 128 (two 64-col subtiles), 2-stage A (16KB) + 2-stage B (32KB).
#define G1_OFF_B1 0
#define G1_OFF_A  1024
#define G1_OFF_BW (1024 + 32768)
#define G1_SMEM   (1024 + 32768 + 65536)

__device__ __forceinline__ float4 app4(const int* p, float e0, float e1, float e2) {
    int4 a = *(const int4*)p;
    return make_float4(a.x == 0 ? e0 : (a.x == 1 ? e1 : e2),
                       a.y == 0 ? e0 : (a.y == 1 ? e1 : e2),
                       a.z == 0 ? e0 : (a.z == 1 ? e1 : e2),
                       a.w == 0 ? e0 : (a.w == 1 ? e1 : e2));
}

__device__ __forceinline__ void g1_lda(float4 (&pf)[4], const float* __restrict__ xr,
                                       const int* __restrict__ ar,
                                       float e0, float e1, float e2, int k0, int kq0) {
    if (k0 + 63 < XF) {
        #pragma unroll
        for (int j = 0; j < 4; j++) pf[j] = *(const float4*)(xr + k0 + kq0 + j * 4);
    } else {
        #pragma unroll
        for (int j = 0; j < 4; j++) {
            const int k = k0 + kq0 + j * 4;
            if (k + 3 < XF)       pf[j] = *(const float4*)(xr + k);
            else if (k < FEATR)   pf[j] = app4(ar + (k - XF), e0, e1, e2);
            else                  pf[j] = make_float4(0.f, 0.f, 0.f, 0.f);
        }
    }
}
__device__ __forceinline__ void g1_sta(const float4 (&pf)[4], char* Ab, int row, int kq0) {
    #pragma unroll
    for (int q = 0; q < 2; q++) {
        const float4 f0 = pf[q * 2], f1 = pf[q * 2 + 1];
        uint4 h;
        h.x = packh2(f0.x, f0.y);
        h.y = packh2(f0.z, f0.w);
        h.z = packh2(f1.x, f1.y);
        h.w = packh2(f1.z, f1.w);
        const uint32_t off = SWZ((uint32_t)(row * 128 + (kq0 + q * 8) * 2));
        *(uint4*)(Ab + off) = h;
    }
}

__device__ __forceinline__ void g1_ldb(const uint32_t (&bofs)[4],
                                       const __half* const (&gw)[4],
                                       uint32_t dst, int koff) {
    #pragma unroll
    for (int i = 0; i < 4; i++) cpa16(dst + bofs[i], gw[i] + koff);
}

__global__ __launch_bounds__(256, 2)
void gemm1_kernel(const float* __restrict__ x, const int* __restrict__ apps) {
    extern __shared__ char sm[];
    const uint32_t su = smem_to_u32(sm);
    const int tid = threadIdx.x;
    const int wid = tid >> 5;
    const int lane = tid & 31;
    const int b0 = blockIdx.x * 64;

    float* sb1 = (float*)(sm + G1_OFF_B1);
    if (tid < 128) sb1[tid] = g_b1adj[tid];

    char* pA[2] = { sm + G1_OFF_A, sm + G1_OFF_A + 16384 };
    const uint32_t uA[2] = { su + G1_OFF_A, su + G1_OFF_A + 16384 };
    const uint32_t uB[2] = { su + G1_OFF_BW, su + G1_OFF_BW + 32768 };

    const int arow = tid >> 2;
    const int kq0  = (tid & 3) * 16;
    const float* xr = x + (size_t)(b0 + arow) * XF;
    const int*   ar = apps + (size_t)(b0 + arow) * NNODES;
    const float e0 = g_ew[0], e1 = g_ew[1], e2 = g_ew[2];

    uint32_t bofs[4];
    const __half* gw[4];
    #pragma unroll
    for (int i = 0; i < 4; i++) {
        const int v = tid + i * 256;
        bofs[i] = SWZ((uint32_t)((v >> 3) * 128 + (v & 7) * 16));
        gw[i] = g_w1t + (size_t)(v >> 3) * FEATP + (v & 7) * 8;
    }

    const int wm = (wid >> 2) * 32;
    const int wn = (wid & 3) * 32;

    float C[2][4][4];
    #pragma unroll
    for (int i = 0; i < 2; i++)
        #pragma unroll
        for (int j = 0; j < 4; j++)
            #pragma unroll
            for (int q = 0; q < 4; q++) C[i][j][q] = 0.f;

    float4 pf[4];
    // ---- prologue ----
    g1_ldb(bofs, gw, uB[0], 0);
    g1_ldb(bofs, gw, uB[0] + 16384, 64);
    CPA_COMMIT();
    g1_lda(pf, xr, ar, e0, e1, e2, 0, kq0);
    g1_sta(pf, pA[0], arow, kq0);
    g1_lda(pf, xr, ar, e0, e1, e2, 64, kq0);
    g1_sta(pf, pA[0] + 8192, arow, kq0);
    CPA_WAIT0();
    __syncthreads();

    // ---- mainloop: 22 iterations of K=128 ----
    for (int t = 0; t < NT1; t++) {
        const int cur = t & 1;
        const int nb = cur ^ 1;
        const bool more = (t + 1 < NT1);
        float4 pfl[4];
        if (more) {
            const int koff = (t + 1) * 128;
            g1_ldb(bofs, gw, uB[nb], koff);
            g1_ldb(bofs, gw, uB[nb] + 16384, koff + 64);
            CPA_COMMIT();
            g1_lda(pfl, xr, ar, e0, e1, e2, koff, kq0);
        }
        mma_chunk1<4>(C, uA[cur], uB[cur], wm, wn, lane);
        if (more) {
            g1_sta(pfl, pA[nb], arow, kq0);
            g1_lda(pfl, xr, ar, e0, e1, e2, (t + 1) * 128 + 64, kq0);
        }
        mma_chunk1<4>(C, uA[cur] + 8192, uB[cur] + 16384, wm, wn, lane);
        if (more) {
            g1_sta(pfl, pA[nb] + 8192, arow, kq0);
            CPA_WAIT0();
        }
        __syncthreads();
    }

    // ---- epilogue: bias + softplus -> g_a1h (fp16) ----
    {
        const int r0 = wm + (lane >> 2);
        const int c0 = wn + (lane & 3) * 2;
        #pragma unroll
        for (int mt = 0; mt < 2; mt++) {
            #pragma unroll
            for (int nt = 0; nt < 4; nt++) {
                const int c = c0 + nt * 8;
                const float bb0 = sb1[c], bb1 = sb1[c + 1];
                uint32_t p01 = packh2(softplusf(C[mt][nt][0] + bb0),
                                      softplusf(C[mt][nt][1] + bb1));
                uint32_t p23 = packh2(softplusf(C[mt][nt][2] + bb0),
                                      softplusf(C[mt][nt][3] + bb1));
                *(uint32_t*)(g_a1h + (size_t)(b0 + r0 + mt * 16) * 128 + c) = p01;
                *(uint32_t*)(g_a1h + (size_t)(b0 + r0 + mt * 16 + 8) * 128 + c) = p23;
            }
        }
    }
}

// ================= kernel 2: layers 2-4 (fast-math, upfront loads) =================
#define M2_OFF_B2 0
#define M2_OFF_B3 512
#define M2_OFF_B4 768
#define M2_OFF_W4 1024
#define M2_OFF_A  2048                       // a tiles: 2 x 8KB (a1 -> a2 -> a3)
#define M2_OFF_W2 (2048 + 16384)             // 2 x 16KB
#define M2_OFF_W3 (2048 + 16384 + 32768)     // 2 x 8KB
#define M2_SMEM   (2048 + 16384 + 32768 + 16384)

__device__ __forceinline__ void m2_cpa_W(const __half* __restrict__ W, int ldk,
                                         int k0, uint32_t dst, int nrows, int tid) {
    const int nv = nrows * 8;
    for (int v = tid; v < nv; v += 256) {
        const int n = v >> 3, kq = (v & 7) * 8;
        cpa16(dst + SWZ((uint32_t)(n * 128 + kq * 2)), W + (size_t)n * ldk + k0 + kq);
    }
}

__device__ __forceinline__ void m2_epi(float (&C)[2][4][4], const float* bias,
                                       char* dst, int wm_base, int wn_base, int lane) {
    const int r0 = wm_base + (lane >> 2);
    const int c0 = wn_base + (lane & 3) * 2;
    #pragma unroll
    for (int mt = 0; mt < 2; mt++) {
        #pragma unroll
        for (int nt = 0; nt < 4; nt++) {
            const int n = c0 + nt * 8;
            const int chunk = n >> 6, col = n & 63;
            const float b0 = bias[n], b1 = bias[n + 1];
            char* td = dst + chunk * 8192;
            uint32_t p01 = packh2(softplusf(C[mt][nt][0] + b0),
                                  softplusf(C[mt][nt][1] + b1));
            uint32_t p23 = packh2(softplusf(C[mt][nt][2] + b0),
                                  softplusf(C[mt][nt][3] + b1));
            *(uint32_t*)(td + SWZ((uint32_t)((r0 + mt * 16) * 128 + col * 2))) = p01;
            *(uint32_t*)(td + SWZ((uint32_t)((r0 + mt * 16 + 8) * 128 + col * 2))) = p23;
        }
    }
}

__global__ __launch_bounds__(256, 2)
void mlp2_kernel(const float* __restrict__ b2g, const float* __restrict__ b3g,
                 const float* __restrict__ b4g, const float* __restrict__ W4g,
                 float* __restrict__ out) {
    extern __shared__ char sm[];
    const uint32_t su = smem_to_u32(sm);
    const int tid = threadIdx.x;
    const int wid = tid >> 5;
    const int lane = tid & 31;
    const int b0 = blockIdx.x * 64;

    float* sb2 = (float*)(sm + M2_OFF_B2);
    float* sb3 = (float*)(sm + M2_OFF_B3);
    float* sb4 = (float*)(sm + M2_OFF_B4);
    float* sW4 = (float*)(sm + M2_OFF_W4);
    if (tid < 128) { sb2[tid] = b2g[tid]; sW4[tid] = W4g[tid]; }
    if (tid < 64) sb3[tid] = b3g[tid];
    if (tid < 2) sb4[tid] = b4g[tid];

    const uint32_t uA[2]  = { su + M2_OFF_A,  su + M2_OFF_A + 8192 };
    const uint32_t uW2[2] = { su + M2_OFF_W2, su + M2_OFF_W2 + 16384 };
    const uint32_t uW3[2] = { su + M2_OFF_W3, su + M2_OFF_W3 + 8192 };

    // load everything up front: a1, W2, W3
    m2_cpa_W(g_a1h + (size_t)b0 * 128, 128, 0,  uA[0], 64, tid);
    m2_cpa_W(g_a1h + (size_t)b0 * 128, 128, 64, uA[1], 64, tid);
    m2_cpa_W(g_w2t, 128, 0,  uW2[0], 128, tid);
    m2_cpa_W(g_w2t, 128, 64, uW2[1], 128, tid);
    m2_cpa_W(g_w3t, 128, 0,  uW3[0], 64, tid);
    m2_cpa_W(g_w3t, 128, 64, uW3[1], 64, tid);
    CPA_COMMIT();
    CPA_WAIT0();
    __syncthreads();

    const int wm = (wid >> 2) * 32;
    const int wn = (wid & 3) * 32;

    // GEMM2
    float C[2][4][4];
    #pragma unroll
    for (int i = 0; i < 2; i++)
        #pragma unroll
        for (int j = 0; j < 4; j++)
            #pragma unroll
            for (int q = 0; q < 4; q++) C[i][j][q] = 0.f;
    #pragma unroll
    for (int c = 0; c < 2; c++)
        mma_chunk1<4>(C, uA[c], uW2[c], wm, wn, lane);
    __syncthreads();

    // epi2 -> a2 tiles (A region)
    m2_epi(C, sb2, sm + M2_OFF_A, wm, wn, lane);
    __syncthreads();

    // GEMM3 (N=64), warp tile 32x16
    const int wn3 = (wid & 3) * 16;
    float C3[2][2][4];
    #pragma unroll
    for (int i = 0; i < 2; i++)
        #pragma unroll
        for (int j = 0; j < 2; j++)
            #pragma unroll
            for (int q = 0; q < 4; q++) C3[i][j][q] = 0.f;
    #pragma unroll
    for (int c = 0; c < 2; c++)
        mma_chunk1<2>(C3, uA[c], uW3[c], wm, wn3, lane);
    __syncthreads();

    // epi3: tanhshrink -> a3 fp32 [64][68] (A region)
    {
        float* a3 = (float*)(sm + M2_OFF_A);
        const int r0 = wm + (lane >> 2);
        const int c0 = wn3 + (lane & 3) * 2;
        #pragma unroll
        for (int mt = 0; mt < 2; mt++) {
            #pragma unroll
            for (int nt = 0; nt < 2; nt++) {
                const int n = c0 + nt * 8;
                const float b0v = sb3[n], b1v = sb3[n + 1];
                float v;
                v = C3[mt][nt][0] + b0v; a3[(r0 + mt * 16) * 68 + n]     = v - fast_tanhf(v);
                v = C3[mt][nt][1] + b1v; a3[(r0 + mt * 16) * 68 + n + 1] = v - fast_tanhf(v);
                v = C3[mt][nt][2] + b0v; a3[(r0 + mt * 16 + 8) * 68 + n]     = v - fast_tanhf(v);
                v = C3[mt][nt][3] + b1v; a3[(r0 + mt * 16 + 8) * 68 + n + 1] = v - fast_tanhf(v);
            }
        }
    }
    __syncthreads();

    // layer 4 + sigmoid
    if (tid < 128) {
        const float* a3 = (const float*)(sm + M2_OFF_A);
        const int row = tid >> 1;
        const int c = tid & 1;
        float s = sb4[c];
        #pragma unroll
        for (int k = 0; k < 64; k++) s += a3[row * 68 + k] * sW4[k * 2 + c];
        out[(size_t)(b0 + row) * 2 + c] = __fdividef(1.f, 1.f + __expf(-s));
    }
}

// ---------------- launch ----------------
extern "C" void kernel_launch(void* const* d_in, const int* in_sizes, int n_in,
                              void* d_out, int out_size) {
    const float* x    = (const float*)d_in[0];
    const int*   apps = (const int*)d_in[1];
    const int*   es   = (const int*)d_in[2];
    const int*   ed   = (const int*)d_in[3];
    const float* emb  = (const float*)d_in[4];
    const float* gcw  = (const float*)d_in[5];
    const float* gcb  = (const float*)d_in[6];
    const float* W1   = (const float*)d_in[7];
    const float* b1   = (const float*)d_in[8];
    const float* W2   = (const float*)d_in[9];
    const float* b2   = (const float*)d_in[10];
    const float* W3   = (const float*)d_in[11];
    const float* b3   = (const float*)d_in[12];
    const float* W4   = (const float*)d_in[13];
    const float* b4   = (const float*)d_in[14];
    float* out = (float*)d_out;

    cudaFuncSetAttribute(gemm1_kernel, cudaFuncAttributeMaxDynamicSharedMemorySize, G1_SMEM);
    cudaFuncSetAttribute(mlp2_kernel, cudaFuncAttributeMaxDynamicSharedMemorySize, M2_SMEM);

    prep1_kernel<<<1, 256>>>(es, ed, emb, gcw, gcb, W1, b1);
    prep2_kernel<<<448, 256>>>(es, ed, W1, W2, W3);
    prep3_kernel<<<100, 256>>>();
    gemm1_kernel<<<B_TOTAL / 64, 256, G1_SMEM>>>(x, apps);
    mlp2_kernel<<<B_TOTAL / 64, 256, M2_SMEM>>>(b2, b3, b4, W4, out);
}

// round 16
// speedup vs baseline: 1.2112x; 1.0400x over previous
#include <cuda_runtime.h>
#include <cuda_fp16.h>
#include <cstdint>

#define B_TOTAL 16384
#define NNODES  200
#define NEDGES  800
#define XF      2600
#define FEATR   2800
#define FEATP   2816           // K padded to 22*128
#define NT1     (FEATP / 128)  // 22

// ---------------- device scratch ----------------
__device__ __align__(16) __half g_a1h[(size_t)B_TOTAL * 128];
__device__ float g_ew[3];
__device__ float g_b1adj[128];
__device__ __align__(16) __half g_w1t[128 * FEATP];    // fp16, transposed [n][k]
__device__ __align__(16) __half g_w2t[128 * 128];
__device__ __align__(16) __half g_w3t[64 * 128];

// ---------------- helpers ----------------
__device__ __forceinline__ uint32_t smem_to_u32(const void* p) {
    uint32_t a;
    asm("{ .reg .u64 t; cvta.to.shared.u64 t, %1; cvt.u32.u64 %0, t; }" : "=r"(a) : "l"(p));
    return a;
}
#define SWZ(off) ((off) ^ (((off) >> 3) & 0x70))

__device__ __forceinline__ void ldsm4(uint32_t r[4], uint32_t addr) {
    asm volatile("ldmatrix.sync.aligned.m8n8.x4.shared.b16 {%0,%1,%2,%3}, [%4];"
                 : "=r"(r[0]), "=r"(r[1]), "=r"(r[2]), "=r"(r[3]) : "r"(addr));
}
__device__ __forceinline__ void mma16816h(float c[4], const uint32_t a[4],
                                          uint32_t b0, uint32_t b1) {
    asm volatile("mma.sync.aligned.m16n8k16.row.col.f32.f16.f16.f32 "
                 "{%0,%1,%2,%3}, {%4,%5,%6,%7}, {%8,%9}, {%0,%1,%2,%3};"
                 : "+f"(c[0]), "+f"(c[1]), "+f"(c[2]), "+f"(c[3])
                 : "r"(a[0]), "r"(a[1]), "r"(a[2]), "r"(a[3]), "r"(b0), "r"(b1));
}
__device__ __forceinline__ void cpa16(uint32_t dst, const void* src) {
    asm volatile("cp.async.cg.shared.global [%0], [%1], 16;" :: "r"(dst), "l"(src));
}
#define CPA_COMMIT() asm volatile("cp.async.commit_group;" ::: "memory")
#define CPA_WAIT0()  asm volatile("cp.async.wait_group 0;" ::: "memory")

__device__ __forceinline__ uint32_t packh2(float a, float b) {
    __half2 h = __floats2half2_rn(a, b);
    return *reinterpret_cast<uint32_t*>(&h);
}
// fast softplus: MUFU-backed
__device__ __forceinline__ float softplusf(float x) {
    return fmaxf(x, 0.f) + __logf(1.f + __expf(-fabsf(x)));
}
// fast tanh: saturates correctly at +/-inf
__device__ __forceinline__ float fast_tanhf(float v) {
    float e = __expf(2.f * v);
    return 1.f - __fdividef(2.f, e + 1.f);
}

// ---------------- MMA over a 64-col K subtile: 2M x (NTILES*8) ----------------
template<int NTILES>
__device__ __forceinline__ void mma_chunk1(float (&C)[2][NTILES][4],
                                           uint32_t a_u, uint32_t b_u,
                                           int wm_base, int wn_base, int lane) {
    const int lr = (lane & 7) + ((lane >> 3) & 1) * 8;
    const int lh = (lane >> 4) * 16;
    #pragma unroll
    for (int kk = 0; kk < 4; kk++) {
        uint32_t a[2][4];
        #pragma unroll
        for (int mt = 0; mt < 2; mt++) {
            uint32_t off = SWZ((uint32_t)((wm_base + mt * 16 + lr) * 128 + kk * 32 + lh));
            ldsm4(a[mt], a_u + off);
        }
        #pragma unroll
        for (int ng = 0; ng < NTILES / 2; ng++) {
            uint32_t off = SWZ((uint32_t)((wn_base + ng * 16 + lr) * 128 + kk * 32 + lh));
            uint32_t b[4];
            ldsm4(b, b_u + off);
            #pragma unroll
            for (int half = 0; half < 2; half++) {
                const int nt = ng * 2 + half;
                #pragma unroll
                for (int mt = 0; mt < 2; mt++)
                    mma16816h(C[mt][nt], a[mt], b[half], b[half + 2]);
            }
        }
    }
}

// ================= single prep kernel =================
// blocks 0..447   : grid-stride weight transposes (W1 x-rows, W2, W3)
// blocks 448..455 : graph fold — 25 src nodes each via LOCAL CSR, write fp16
//                   directly into w1t rows [2600,2800)
// block  456      : ew + b1adj
#define TRB   448
#define FOLDB 8
#define SPB   25
__global__ void prep_kernel(const int* __restrict__ es, const int* __restrict__ ed,
                            const float* __restrict__ emb, const float* __restrict__ gcw,
                            const float* __restrict__ gcb,
                            const float* __restrict__ W1, const float* __restrict__ b1,
                            const float* __restrict__ W2, const float* __restrict__ W3) {
    const int b = blockIdx.x;
    const int tid = threadIdx.x;
    if (b < TRB) {
        const int gtid = b * 256 + tid;
        const int gsz = TRB * 256;
        const int T1 = 128 * FEATP, T2 = 128 * 128, T3 = 64 * 128;
        for (int i = gtid; i < T1 + T2 + T3; i += gsz) {
            float v;
            __half* ph;
            if (i < T1) {
                int k = i % FEATP;
                int n = i / FEATP;
                if (k >= XF && k < FEATR) continue;   // graph rows: fold blocks
                v = (k < XF) ? W1[(size_t)k * 128 + n] : 0.f;
                ph = g_w1t + i;
            } else if (i < T1 + T2) {
                int j = i - T1;
                int n = j >> 7, k = j & 127;
                v = W2[k * 128 + n];
                ph = g_w2t + j;
            } else {
                int j = i - T1 - T2;
                int n = j >> 7, k = j & 127;
                v = W3[k * 64 + n];
                ph = g_w3t + j;
            }
            *ph = __float2half_rn(v);
        }
    } else if (b < TRB + FOLDB) {
        __shared__ int ses[NEDGES], sed[NEDGES];
        __shared__ int cnto[NNODES], cnti[NNODES];
        __shared__ float ndst[NNODES];
        __shared__ int off[SPB + 1], pos[SPB];
        __shared__ int csr_d[NEDGES];
        for (int i = tid; i < NEDGES; i += 256) { ses[i] = es[i]; sed[i] = ed[i]; }
        for (int n = tid; n < NNODES; n += 256) { cnto[n] = 0; cnti[n] = 0; }
        __syncthreads();
        for (int e = tid; e < NEDGES; e += 256) {
            atomicAdd(&cnto[ses[e]], 1);
            atomicAdd(&cnti[sed[e]], 1);
        }
        __syncthreads();
        for (int n = tid; n < NNODES; n += 256)
            ndst[n] = rsqrtf((float)max(cnti[n], 1));
        const int s0 = (b - TRB) * SPB;
        if (tid == 0) {
            int o = 0;
            for (int i = 0; i < SPB; i++) { off[i] = o; pos[i] = o; o += cnto[s0 + i]; }
            off[SPB] = o;
        }
        __syncthreads();
        for (int e = tid; e < NEDGES; e += 256) {
            const int s = ses[e];
            if (s >= s0 && s < s0 + SPB) {
                const int p = atomicAdd(&pos[s - s0], 1);
                csr_d[p] = sed[e];
            }
        }
        __syncthreads();
        // items: (sl, n); lanes consecutive in n -> coalesced W1 reads
        for (int idx = tid; idx < SPB * 128; idx += 256) {
            const int sl = idx >> 7;
            const int n  = idx & 127;
            const int s  = s0 + sl;
            const float nsrc = rsqrtf((float)max(cnto[s], 1));
            float acc = 0.f;
            const int e0 = off[sl], e1 = off[sl + 1];
            for (int e = e0; e < e1; e++) {
                const int d = csr_d[e];
                acc += ndst[d] * W1[(size_t)(XF + d) * 128 + n];
            }
            g_w1t[(size_t)n * FEATP + XF + s] = __float2half_rn(nsrc * acc);
        }
    } else {
        if (tid < 3) {
            float s = 0.f;
            #pragma unroll
            for (int j = 0; j < 5; j++) s += emb[tid * 5 + j] * gcw[j];
            g_ew[tid] = s;
        }
        if (tid < 128) {
            float s0 = 0.f, s1 = 0.f;
            for (int d = 0; d < NNODES; d += 2) {
                s0 += W1[(size_t)(XF + d) * 128 + tid];
                s1 += W1[(size_t)(XF + d + 1) * 128 + tid];
            }
            g_b1adj[tid] = b1[tid] + gcb[0] * (s0 + s1);
        }
    }
}

// ================= GEMM1: a1 = softplus([x|hw] @ W1' + b1adj) -> fp16 =================
#define G1_OFF_B1 0
#define G1_OFF_A  1024
#define G1_OFF_BW (1024 + 32768)
#define G1_SMEM   (1024 + 32768 + 65536)

__device__ __forceinline__ float4 app4(const int* p, float e0, float e1, float e2) {
    int4 a = *(const int4*)p;
    return make_float4(a.x == 0 ? e0 : (a.x == 1 ? e1 : e2),
                       a.y == 0 ? e0 : (a.y == 1 ? e1 : e2),
                       a.z == 0 ? e0 : (a.z == 1 ? e1 : e2),
                       a.w == 0 ? e0 : (a.w == 1 ? e1 : e2));
}

__device__ __forceinline__ void g1_lda(float4 (&pf)[4], const float* __restrict__ xr,
                                       const int* __restrict__ ar,
                                       float e0, float e1, float e2, int k0, int kq0) {
    if (k0 + 63 < XF) {
        #pragma unroll
        for (int j = 0; j < 4; j++) pf[j] = *(const float4*)(xr + k0 + kq0 + j * 4);
    } else {
        #pragma unroll
        for (int j = 0; j < 4; j++) {
            const int k = k0 + kq0 + j * 4;
            if (k + 3 < XF)       pf[j] = *(const float4*)(xr + k);
            else if (k < FEATR)   pf[j] = app4(ar + (k - XF), e0, e1, e2);
            else                  pf[j] = make_float4(0.f, 0.f, 0.f, 0.f);
        }
    }
}
__device__ __forceinline__ void g1_sta(const float4 (&pf)[4], char* Ab, int row, int kq0) {
    #pragma unroll
    for (int q = 0; q < 2; q++) {
        const float4 f0 = pf[q * 2], f1 = pf[q * 2 + 1];
        uint4 h;
        h.x = packh2(f0.x, f0.y);
        h.y = packh2(f0.z, f0.w);
        h.z = packh2(f1.x, f1.y);
        h.w = packh2(f1.z, f1.w);
        const uint32_t off = SWZ((uint32_t)(row * 128 + (kq0 + q * 8) * 2));
        *(uint4*)(Ab + off) = h;
    }
}

__device__ __forceinline__ void g1_ldb(const uint32_t (&bofs)[4],
                                       const __half* const (&gw)[4],
                                       uint32_t dst, int koff) {
    #pragma unroll
    for (int i = 0; i < 4; i++) cpa16(dst + bofs[i], gw[i] + koff);
}

__global__ __launch_bounds__(256, 2)
void gemm1_kernel(const float* __restrict__ x, const int* __restrict__ apps) {
    extern __shared__ char sm[];
    const uint32_t su = smem_to_u32(sm);
    const int tid = threadIdx.x;
    const int wid = tid >> 5;
    const int lane = tid & 31;
    const int b0 = blockIdx.x * 64;

    float* sb1 = (float*)(sm + G1_OFF_B1);
    if (tid < 128) sb1[tid] = g_b1adj[tid];

    char* pA[2] = { sm + G1_OFF_A, sm + G1_OFF_A + 16384 };
    const uint32_t uA[2] = { su + G1_OFF_A, su + G1_OFF_A + 16384 };
    const uint32_t uB[2] = { su + G1_OFF_BW, su + G1_OFF_BW + 32768 };

    const int arow = tid >> 2;
    const int kq0  = (tid & 3) * 16;
    const float* xr = x + (size_t)(b0 + arow) * XF;
    const int*   ar = apps + (size_t)(b0 + arow) * NNODES;
    const float e0 = g_ew[0], e1 = g_ew[1], e2 = g_ew[2];

    uint32_t bofs[4];
    const __half* gw[4];
    #pragma unroll
    for (int i = 0; i < 4; i++) {
        const int v = tid + i * 256;
        bofs[i] = SWZ((uint32_t)((v >> 3) * 128 + (v & 7) * 16));
        gw[i] = g_w1t + (size_t)(v >> 3) * FEATP + (v & 7) * 8;
    }

    const int wm = (wid >> 2) * 32;
    const int wn = (wid & 3) * 32;

    float C[2][4][4];
    #pragma unroll
    for (int i = 0; i < 2; i++)
        #pragma unroll
        for (int j = 0; j < 4; j++)
            #pragma unroll
            for (int q = 0; q < 4; q++) C[i][j][q] = 0.f;

    float4 pf[4];
    // ---- prologue ----
    g1_ldb(bofs, gw, uB[0], 0);
    g1_ldb(bofs, gw, uB[0] + 16384, 64);
    CPA_COMMIT();
    g1_lda(pf, xr, ar, e0, e1, e2, 0, kq0);
    g1_sta(pf, pA[0], arow, kq0);
    g1_lda(pf, xr, ar, e0, e1, e2, 64, kq0);
    g1_sta(pf, pA[0] + 8192, arow, kq0);
    CPA_WAIT0();
    __syncthreads();

    // ---- mainloop: 22 iterations of K=128 ----
    for (int t = 0; t < NT1; t++) {
        const int cur = t & 1;
        const int nb = cur ^ 1;
        const bool more = (t + 1 < NT1);
        float4 pfl[4];
        if (more) {
            const int koff = (t + 1) * 128;
            g1_ldb(bofs, gw, uB[nb], koff);
            g1_ldb(bofs, gw, uB[nb] + 16384, koff + 64);
            CPA_COMMIT();
            g1_lda(pfl, xr, ar, e0, e1, e2, koff, kq0);
        }
        mma_chunk1<4>(C, uA[cur], uB[cur], wm, wn, lane);
        if (more) {
            g1_sta(pfl, pA[nb], arow, kq0);
            g1_lda(pfl, xr, ar, e0, e1, e2, (t + 1) * 128 + 64, kq0);
        }
        mma_chunk1<4>(C, uA[cur] + 8192, uB[cur] + 16384, wm, wn, lane);
        if (more) {
            g1_sta(pfl, pA[nb] + 8192, arow, kq0);
            CPA_WAIT0();
        }
        __syncthreads();
    }

    // ---- epilogue: bias + softplus -> g_a1h (fp16) ----
    {
        const int r0 = wm + (lane >> 2);
        const int c0 = wn + (lane & 3) * 2;
        #pragma unroll
        for (int mt = 0; mt < 2; mt++) {
            #pragma unroll
            for (int nt = 0; nt < 4; nt++) {
                const int c = c0 + nt * 8;
                const float bb0 = sb1[c], bb1 = sb1[c + 1];
                uint32_t p01 = packh2(softplusf(C[mt][nt][0] + bb0),
                                      softplusf(C[mt][nt][1] + bb1));
                uint32_t p23 = packh2(softplusf(C[mt][nt][2] + bb0),
                                      softplusf(C[mt][nt][3] + bb1));
                *(uint32_t*)(g_a1h + (size_t)(b0 + r0 + mt * 16) * 128 + c) = p01;
                *(uint32_t*)(g_a1h + (size_t)(b0 + r0 + mt * 16 + 8) * 128 + c) = p23;
            }
        }
    }
}

// ================= kernel 2: layers 2-4 (fast-math, upfront loads) =================
#define M2_OFF_B2 0
#define M2_OFF_B3 512
#define M2_OFF_B4 768
#define M2_OFF_W4 1024
#define M2_OFF_A  2048                       // a tiles: 2 x 8KB (a1 -> a2 -> a3)
#define M2_OFF_W2 (2048 + 16384)             // 2 x 16KB
#define M2_OFF_W3 (2048 + 16384 + 32768)     // 2 x 8KB
#define M2_SMEM   (2048 + 16384 + 32768 + 16384)

__device__ __forceinline__ void m2_cpa_W(const __half* __restrict__ W, int ldk,
                                         int k0, uint32_t dst, int nrows, int tid) {
    const int nv = nrows * 8;
    for (int v = tid; v < nv; v += 256) {
        const int n = v >> 3, kq = (v & 7) * 8;
        cpa16(dst + SWZ((uint32_t)(n * 128 + kq * 2)), W + (size_t)n * ldk + k0 + kq);
    }
}

__device__ __forceinline__ void m2_epi(float (&C)[2][4][4], const float* bias,
                                       char* dst, int wm_base, int wn_base, int lane) {
    const int r0 = wm_base + (lane >> 2);
    const int c0 = wn_base + (lane & 3) * 2;
    #pragma unroll
    for (int mt = 0; mt < 2; mt++) {
        #pragma unroll
        for (int nt = 0; nt < 4; nt++) {
            const int n = c0 + nt * 8;
            const int chunk = n >> 6, col = n & 63;
            const float b0 = bias[n], b1 = bias[n + 1];
            char* td = dst + chunk * 8192;
            uint32_t p01 = packh2(softplusf(C[mt][nt][0] + b0),
                                  softplusf(C[mt][nt][1] + b1));
            uint32_t p23 = packh2(softplusf(C[mt][nt][2] + b0),
                                  softplusf(C[mt][nt][3] + b1));
            *(uint32_t*)(td + SWZ((uint32_t)((r0 + mt * 16) * 128 + col * 2))) = p01;
            *(uint32_t*)(td + SWZ((uint32_t)((r0 + mt * 16 + 8) * 128 + col * 2))) = p23;
        }
    }
}

__global__ __launch_bounds__(256, 2)
void mlp2_kernel(const float* __restrict__ b2g, const float* __restrict__ b3g,
                 const float* __restrict__ b4g, const float* __restrict__ W4g,
                 float* __restrict__ out) {
    extern __shared__ char sm[];
    const uint32_t su = smem_to_u32(sm);
    const int tid = threadIdx.x;
    const int wid = tid >> 5;
    const int lane = tid & 31;
    const int b0 = blockIdx.x * 64;

    float* sb2 = (float*)(sm + M2_OFF_B2);
    float* sb3 = (float*)(sm + M2_OFF_B3);
    float* sb4 = (float*)(sm + M2_OFF_B4);
    float* sW4 = (float*)(sm + M2_OFF_W4);
    if (tid < 128) { sb2[tid] = b2g[tid]; sW4[tid] = W4g[tid]; }
    if (tid < 64) sb3[tid] = b3g[tid];
    if (tid < 2) sb4[tid] = b4g[tid];

    const uint32_t uA[2]  = { su + M2_OFF_A,  su + M2_OFF_A + 8192 };
    const uint32_t uW2[2] = { su + M2_OFF_W2, su + M2_OFF_W2 + 16384 };
    const uint32_t uW3[2] = { su + M2_OFF_W3, su + M2_OFF_W3 + 8192 };

    m2_cpa_W(g_a1h + (size_t)b0 * 128, 128, 0,  uA[0], 64, tid);
    m2_cpa_W(g_a1h + (size_t)b0 * 128, 128, 64, uA[1], 64, tid);
    m2_cpa_W(g_w2t, 128, 0,  uW2[0], 128, tid);
    m2_cpa_W(g_w2t, 128, 64, uW2[1], 128, tid);
    m2_cpa_W(g_w3t, 128, 0,  uW3[0], 64, tid);
    m2_cpa_W(g_w3t, 128, 64, uW3[1], 64, tid);
    CPA_COMMIT();
    CPA_WAIT0();
    __syncthreads();

    const int wm = (wid >> 2) * 32;
    const int wn = (wid & 3) * 32;

    float C[2][4][4];
    #pragma unroll
    for (int i = 0; i < 2; i++)
        #pragma unroll
        for (int j = 0; j < 4; j++)
            #pragma unroll
            for (int q = 0; q < 4; q++) C[i][j][q] = 0.f;
    #pragma unroll
    for (int c = 0; c < 2; c++)
        mma_chunk1<4>(C, uA[c], uW2[c], wm, wn, lane);
    __syncthreads();

    m2_epi(C, sb2, sm + M2_OFF_A, wm, wn, lane);
    __syncthreads();

    const int wn3 = (wid & 3) * 16;
    float C3[2][2][4];
    #pragma unroll
    for (int i = 0; i < 2; i++)
        #pragma unroll
        for (int j = 0; j < 2; j++)
            #pragma unroll
            for (int q = 0; q < 4; q++) C3[i][j][q] = 0.f;
    #pragma unroll
    for (int c = 0; c < 2; c++)
        mma_chunk1<2>(C3, uA[c], uW3[c], wm, wn3, lane);
    __syncthreads();

    {
        float* a3 = (float*)(sm + M2_OFF_A);
        const int r0 = wm + (lane >> 2);
        const int c0 = wn3 + (lane & 3) * 2;
        #pragma unroll
        for (int mt = 0; mt < 2; mt++) {
            #pragma unroll
            for (int nt = 0; nt < 2; nt++) {
                const int n = c0 + nt * 8;
                const float b0v = sb3[n], b1v = sb3[n + 1];
                float v;
                v = C3[mt][nt][0] + b0v; a3[(r0 + mt * 16) * 68 + n]     = v - fast_tanhf(v);
                v = C3[mt][nt][1] + b1v; a3[(r0 + mt * 16) * 68 + n + 1] = v - fast_tanhf(v);
                v = C3[mt][nt][2] + b0v; a3[(r0 + mt * 16 + 8) * 68 + n]     = v - fast_tanhf(v);
                v = C3[mt][nt][3] + b1v; a3[(r0 + mt * 16 + 8) * 68 + n + 1] = v - fast_tanhf(v);
            }
        }
    }
    __syncthreads();

    if (tid < 128) {
        const float* a3 = (const float*)(sm + M2_OFF_A);
        const int row = tid >> 1;
        const int c = tid & 1;
        float s = sb4[c];
        #pragma unroll
        for (int k = 0; k < 64; k++) s += a3[row * 68 + k] * sW4[k * 2 + c];
        out[(size_t)(b0 + row) * 2 + c] = __fdividef(1.f, 1.f + __expf(-s));
    }
}

// ---------------- launch ----------------
extern "C" void kernel_launch(void* const* d_in, const int* in_sizes, int n_in,
                              void* d_out, int out_size) {
    const float* x    = (const float*)d_in[0];
    const int*   apps = (const int*)d_in[1];
    const int*   es   = (const int*)d_in[2];
    const int*   ed   = (const int*)d_in[3];
    const float* emb  = (const float*)d_in[4];
    const float* gcw  = (const float*)d_in[5];
    const float* gcb  = (const float*)d_in[6];
    const float* W1   = (const float*)d_in[7];
    const float* b1   = (const float*)d_in[8];
    const float* W2   = (const float*)d_in[9];
    const float* b2   = (const float*)d_in[10];
    const float* W3   = (const float*)d_in[11];
    const float* b3   = (const float*)d_in[12];
    const float* W4   = (const float*)d_in[13];
    const float* b4   = (const float*)d_in[14];
    float* out = (float*)d_out;

    cudaFuncSetAttribute(gemm1_kernel, cudaFuncAttributeMaxDynamicSharedMemorySize, G1_SMEM);
    cudaFuncSetAttribute(mlp2_kernel, cudaFuncAttributeMaxDynamicSharedMemorySize, M2_SMEM);

    prep_kernel<<<TRB + FOLDB + 1, 256>>>(es, ed, emb, gcw, gcb, W1, b1, W2, W3);
    gemm1_kernel<<<B_TOTAL / 64, 256, G1_SMEM>>>(x, apps);
    mlp2_kernel<<<B_TOTAL / 64, 256, M2_SMEM>>>(b2, b3, b4, W4, out);
}